// round 15
// baseline (speedup 1.0000x reference)
#include <cuda_runtime.h>
#include <cuda_bf16.h>
#include <math.h>
#include <stdint.h>

// ---------------- problem constants ----------------
#define BATCH   2
#define SEQ     2048
#define NTOK    (BATCH * SEQ)        // 4096
#define DMODEL  2048
#define HEADS   16
#define DQK     192
#define DNOPE   128
#define DROPE   64
#define DV      128
#define DQA     1536
#define DKVA    576
#define DKVLAT  512
#define QDIM    (HEADS * DQK)        // 3072
#define KVDIM   (HEADS * (DNOPE + DV)) // 4096
#define ODIM    (HEADS * DV)         // 2048
#define ATT_SCALE 0.07216878364870322f
#define NSM     148
#define GEMM_SLOTS (2 * NSM)         // 2 CTA/SM

// ---------------- scratch ----------------
__device__ float g_qa  [(size_t)NTOK * DQA];
__device__ float g_ckv [(size_t)NTOK * DKVA];
__device__ float g_kvn [(size_t)NTOK * DKVLAT];
__device__ float g_q   [(size_t)NTOK * QDIM];
__device__ float g_kv  [(size_t)NTOK * KVDIM];
__device__ float g_attn[(size_t)NTOK * ODIM];
// tf32-rounded copies (GEMM inner loop consumes raw bits; round upstream)
__device__ float g_hid_r [(size_t)NTOK * DMODEL];
__device__ float g_w_qa  [(size_t)DQA * DMODEL];
__device__ float g_w_kva [(size_t)DKVA * DMODEL];
__device__ float g_w_qb  [(size_t)QDIM * DQA];
__device__ float g_w_kvb [(size_t)KVDIM * DKVLAT];
__device__ float g_w_o   [(size_t)DMODEL * ODIM];

// ---------------- helpers ----------------
__device__ __forceinline__ float to_tf32(float x) {
    float y;
    asm("cvt.rna.tf32.f32 %0, %1;" : "=f"(y) : "f"(x));
    return y;
}

__device__ __forceinline__ uint32_t smem_u32(const void* p) {
    uint32_t a;
    asm("{ .reg .u64 t; cvta.to.shared.u64 t, %1; cvt.u32.u64 %0, t; }" : "=r"(a) : "l"(p));
    return a;
}

__device__ __forceinline__ void mma_tf32(float c[4], const uint32_t a[4], const uint32_t b[2]) {
    asm volatile(
        "mma.sync.aligned.m16n8k8.row.col.f32.tf32.tf32.f32 "
        "{%0,%1,%2,%3}, {%4,%5,%6,%7}, {%8,%9}, {%0,%1,%2,%3};\n"
        : "+f"(c[0]), "+f"(c[1]), "+f"(c[2]), "+f"(c[3])
        : "r"(a[0]), "r"(a[1]), "r"(a[2]), "r"(a[3]), "r"(b[0]), "r"(b[1]));
}

__device__ __forceinline__ void ldsm_x4(uint32_t r[4], uint32_t addr) {
    asm volatile("ldmatrix.sync.aligned.m8n8.x4.shared.b16 {%0,%1,%2,%3}, [%4];"
        : "=r"(r[0]), "=r"(r[1]), "=r"(r[2]), "=r"(r[3]) : "r"(addr));
}

// ---------------- unified dynamic smem ----------------
extern __shared__ char dynsm[];

// ============================================================================
// TF32 GEMM tile body (mma.sync + ldmatrix, 3-stage cp.async pipeline)
// Computes C[bm:bm+128, bn:bn+128] = A[bm:,:K] @ B[bn:,:K]^T
// Inputs MUST be pre-rounded to tf32 (rna). If do_round, output is rna-rounded.
// On exit, all cp.async are drained (safe smem reuse after __syncthreads).
// ============================================================================
#define TBM 128
#define TBN 128
#define TBK 32
#define ASTR 36                          // row stride 144B -> ldmatrix conflict-free
#define NSTG 3
#define STG_FLOATS (TBM * ASTR + TBN * ASTR)   // 9216 floats per stage
#define GEMM_SMEM (NSTG * STG_FLOATS * (int)sizeof(float))  // 110592 B

__device__ __forceinline__ void gemm_tile_body(
    const float* __restrict__ A, const float* __restrict__ Bw,
    float* __restrict__ C, int N, int K, int bm, int bn, int do_round)
{
    float* sm = (float*)dynsm;
    const int tid = threadIdx.x;
    const int wid = tid >> 5, lane = tid & 31;
    const int g = lane >> 2, tg = lane & 3;
    const int wm = (wid >> 2) * 64, wn = (wid & 3) * 32;
    const int NK = K / TBK;

    const int aRowOff = (wm + ((lane >> 3) & 1) * 8 + (lane & 7)) * ASTR + (lane >> 4) * 4;
    const int bRowOff = (wn + (lane >> 4) * 8 + (lane & 7)) * ASTR + ((lane >> 3) & 1) * 4;

#define LOAD_STAGE(c)                                                             \
    {                                                                             \
        const int s_ = (c) % NSTG;                                                \
        float* as_ = sm + s_ * STG_FLOATS;                                        \
        float* bs_ = as_ + TBM * ASTR;                                            \
        _Pragma("unroll")                                                         \
        for (int t_ = 0; t_ < 4; t_++) {                                          \
            int idx_ = tid + t_ * 256;                                            \
            int row_ = idx_ >> 3;                                                 \
            int c4_ = (idx_ & 7) * 4;                                             \
            uint32_t d_ = smem_u32(as_ + row_ * ASTR + c4_);                      \
            const float* s1_ = A + (size_t)(bm + row_) * K + (size_t)(c) * TBK + c4_; \
            asm volatile("cp.async.cg.shared.global.L2::256B [%0], [%1], 16;"     \
                         :: "r"(d_), "l"(s1_));                                   \
        }                                                                         \
        _Pragma("unroll")                                                         \
        for (int t_ = 0; t_ < 4; t_++) {                                          \
            int idx_ = tid + t_ * 256;                                            \
            int row_ = idx_ >> 3;                                                 \
            int c4_ = (idx_ & 7) * 4;                                             \
            int nr_ = bn + row_;                                                  \
            uint32_t d_ = smem_u32(bs_ + row_ * ASTR + c4_);                      \
            const float* s1_ = Bw + (size_t)(nr_ < N ? nr_ : 0) * K + (size_t)(c) * TBK + c4_; \
            unsigned sz_ = (nr_ < N) ? 16u : 0u;                                  \
            asm volatile("cp.async.cg.shared.global.L2::256B [%0], [%1], 16, %2;" \
                         :: "r"(d_), "l"(s1_), "r"(sz_));                         \
        }                                                                         \
        asm volatile("cp.async.commit_group;" ::: "memory");                      \
    }

    float acc[4][4][4];
#pragma unroll
    for (int mt = 0; mt < 4; mt++)
#pragma unroll
        for (int nt = 0; nt < 4; nt++)
#pragma unroll
            for (int i = 0; i < 4; i++) acc[mt][nt][i] = 0.f;

    LOAD_STAGE(0);
    LOAD_STAGE(1);

    for (int cc = 0; cc < NK; cc++) {
        // correct remainder-aware wait: final chunk must be fully landed
        if (cc + 1 < NK) asm volatile("cp.async.wait_group 1;" ::: "memory");
        else             asm volatile("cp.async.wait_group 0;" ::: "memory");
        __syncthreads();
        if (cc + 2 < NK) LOAD_STAGE(cc + 2);

        const int s = cc % NSTG;
        float* as_ = sm + s * STG_FLOATS;
        float* bs_ = as_ + TBM * ASTR;
        const uint32_t aBase = smem_u32(as_ + aRowOff);
        const uint32_t bBase = smem_u32(bs_ + bRowOff);

#pragma unroll
        for (int ks = 0; ks < 4; ks++) {
            const uint32_t kOff = ks * 32;
            uint32_t a[4][4], b[8];
#pragma unroll
            for (int mt = 0; mt < 4; mt++)
                ldsm_x4(a[mt], aBase + mt * (16 * ASTR * 4) + kOff);
            ldsm_x4(&b[0], bBase + kOff);
            ldsm_x4(&b[4], bBase + 16 * ASTR * 4 + kOff);
#pragma unroll
            for (int mt = 0; mt < 4; mt++)
#pragma unroll
                for (int nt = 0; nt < 4; nt++)
                    mma_tf32(acc[mt][nt], a[mt], &b[nt * 2]);
        }
    }
    // all cp.async groups drained (last wait was wait_group 0)

#pragma unroll
    for (int mt = 0; mt < 4; mt++) {
        int r0 = bm + wm + mt * 16 + g;
#pragma unroll
        for (int nt = 0; nt < 4; nt++) {
            int cc = bn + wn + nt * 8 + 2 * tg;
            if (cc < N) {
                float2 v0 = make_float2(acc[mt][nt][0], acc[mt][nt][1]);
                float2 v1 = make_float2(acc[mt][nt][2], acc[mt][nt][3]);
                if (do_round) {
                    v0.x = to_tf32(v0.x); v0.y = to_tf32(v0.y);
                    v1.x = to_tf32(v1.x); v1.y = to_tf32(v1.y);
                }
                *(float2*)(C + (size_t)r0 * N + cc)       = v0;
                *(float2*)(C + (size_t)(r0 + 8) * N + cc) = v1;
            }
        }
    }
#undef LOAD_STAGE
}

// persistent dual GEMM: fixed grid, each CTA strides over the fused tile list.
// GEMM2 may be empty (nt2 == 0) for a single-GEMM launch.
__global__ __launch_bounds__(256, 2) void gemm_persist(
    const float* __restrict__ A1, const float* __restrict__ B1, float* __restrict__ C1,
    int N1, int K1, int ntiles1, int gx1, int round1,
    const float* __restrict__ A2, const float* __restrict__ B2, float* __restrict__ C2,
    int N2, int K2, int ntiles2, int gx2, int round2)
{
    const int total = ntiles1 + ntiles2;
    for (int t0 = blockIdx.x; t0 < total; t0 += gridDim.x) {
        int t = t0;
        const float *A, *Bw;
        float* C;
        int N, K, bm, bn, rnd;
        if (t < ntiles1) {
            A = A1; Bw = B1; C = C1; N = N1; K = K1; rnd = round1;
            bn = (t % gx1) * TBN; bm = (t / gx1) * TBM;
        } else {
            t -= ntiles1;
            A = A2; Bw = B2; C = C2; N = N2; K = K2; rnd = round2;
            bn = (t % gx2) * TBN; bm = (t / gx2) * TBM;
        }
        gemm_tile_body(A, Bw, C, N, K, bm, bn, rnd);
        __syncthreads();   // smem safe for next tile (cp.async already drained)
    }
}

// ---------------- fused tf32 pre-rounding pass (ALL buffers, one launch) ---
__device__ __forceinline__ void round4(const float* in, float* out, int i) {
    float4 v = ((const float4*)in)[i];
    v.x = to_tf32(v.x); v.y = to_tf32(v.y);
    v.z = to_tf32(v.z); v.w = to_tf32(v.w);
    ((float4*)out)[i] = v;
}

__global__ __launch_bounds__(256) void round_all_kernel(
    const float* s0, float* d0, int n0,
    const float* s1, float* d1, int n1,
    const float* s2, float* d2, int n2,
    const float* s3, float* d3, int n3,
    const float* s4, float* d4, int n4,
    const float* s5, float* d5, int n5)
{
    int i = blockIdx.x * 256 + threadIdx.x;
    if (i < n0) { round4(s0, d0, i); return; }  i -= n0;
    if (i < n1) { round4(s1, d1, i); return; }  i -= n1;
    if (i < n2) { round4(s2, d2, i); return; }  i -= n2;
    if (i < n3) { round4(s3, d3, i); return; }  i -= n3;
    if (i < n4) { round4(s4, d4, i); return; }  i -= n4;
    if (i < n5) { round4(s5, d5, i); }
}

// ---------------- fused dual RMSNorm (tf32-rounded output) -----------------
__global__ __launch_bounds__(256) void rmsnorm_dual_kernel(
    const float* __restrict__ in1, float* __restrict__ out1,
    const float* __restrict__ w1, int N1, int is1, int os1, int rows1,
    const float* __restrict__ in2, float* __restrict__ out2,
    const float* __restrict__ w2, int N2, int is2, int os2)
{
    const float* in;  float* out;  const float* w;
    int N, in_stride, out_stride, row = blockIdx.x;
    if (row < rows1) { in = in1; out = out1; w = w1; N = N1; in_stride = is1; out_stride = os1; }
    else { row -= rows1; in = in2; out = out2; w = w2; N = N2; in_stride = is2; out_stride = os2; }

    const float* x = in + (size_t)row * in_stride;
    const int cnt = N >> 8;
    float v[6];
    float ss = 0.f;
    for (int i = 0; i < cnt; i++) {
        v[i] = x[threadIdx.x + (i << 8)];
        ss += v[i] * v[i];
    }
#pragma unroll
    for (int o = 16; o > 0; o >>= 1) ss += __shfl_xor_sync(0xffffffffu, ss, o);
    __shared__ float red[8];
    if ((threadIdx.x & 31) == 0) red[threadIdx.x >> 5] = ss;
    __syncthreads();
    float tot = 0.f;
#pragma unroll
    for (int i = 0; i < 8; i++) tot += red[i];
    const float r = rsqrtf(tot / (float)N + 1e-6f);
    float* y = out + (size_t)row * out_stride;
    for (int i = 0; i < cnt; i++) {
        int c = threadIdx.x + (i << 8);
        y[c] = to_tf32(w[c] * v[i] * r);
    }
}

// ---------------- RoPE (ckv slice written tf32-rounded; q slice raw) -------
__global__ __launch_bounds__(512) void rope_kernel(
    float* __restrict__ q, float* __restrict__ ckv,
    const float* __restrict__ cosb, const float* __restrict__ sinb)
{
    const int tok = blockIdx.x;
    const int t = threadIdx.x;
    const int h = t >> 5;
    const int d = t & 31;
    const float c0 = cosb[(size_t)tok * DROPE + d];
    const float s0 = sinb[(size_t)tok * DROPE + d];
    const float c1 = cosb[(size_t)tok * DROPE + d + 32];
    const float s1 = sinb[(size_t)tok * DROPE + d + 32];
    {
        float* qr = q + (size_t)tok * QDIM + h * DQK + DNOPE;
        float a = qr[d], b = qr[d + 32];
        qr[d]      = a * c0 - b * s0;
        qr[d + 32] = b * c1 + a * s1;
    }
    if (t < 32) {
        float* kr = ckv + (size_t)tok * DKVA + DKVLAT;
        float a = kr[d], b = kr[d + 32];
        kr[d]      = to_tf32(a * c0 - b * s0);   // consumed raw by flash K (cp.async)
        kr[d + 32] = to_tf32(b * c1 + a * s1);
    }
}

// ---------------- Flash attention v4: persistent CTAs ----------------------
// FM=128, FN=32, cp.async double-buffered K/V (pre-rounded in gmem).
// Grid = NSM persistent CTAs; jobs ordered bq-descending for balance.
#define FM 128
#define FN 32
#define SQ_STR 196   // %32 == 4
#define SK_STR 196   // %32 == 4
#define SV_STR 136   // natural V [k][dv], %32 == 8
#define SP_STR 36    // %32 == 4
#define FLASH_SMEM ((FM * SQ_STR + 2 * FN * SK_STR + 2 * FN * SV_STR + FM * SP_STR) * (int)sizeof(float))
#define NQT (SEQ / FM)               // 16
#define NJOBS (NQT * HEADS * BATCH)  // 512

__global__ __launch_bounds__(256) void flash_tf32_kernel(
    const float* __restrict__ q, const float* __restrict__ kvbuf,
    const float* __restrict__ ckv, float* __restrict__ attn_out)
{
    float* fsmem = (float*)dynsm;
    float* sQ = fsmem;                        // 128 x 196
    float* sK = sQ + FM * SQ_STR;             // 2 x 32 x 196
    float* sV = sK + 2 * FN * SK_STR;         // 2 x 32 x 136
    float* sP = sV + 2 * FN * SV_STR;         // 128 x 36

    const int tid = threadIdx.x;
    const int wid = tid >> 5, lane = tid & 31;
    const int g = lane >> 2, tg = lane & 3;
    const int wrow = wid * 16;

    const int aSel = ((lane >> 3) & 1) * 8 + (lane & 7);
    const int aCol = (lane >> 4) * 4;
    const int bSel = (lane >> 4) * 8 + (lane & 7);
    const int bCol = ((lane >> 3) & 1) * 4;

    const uint32_t qBase = smem_u32(sQ + (wrow + aSel) * SQ_STR + aCol);
    const uint32_t pBase = smem_u32(sP + (wrow + aSel) * SP_STR + aCol);
    const int kRowOff = bSel * SK_STR + bCol;

#define LOAD_KV(kt, buf)                                                          \
    {                                                                             \
        float* sKb_ = sK + (buf) * (FN * SK_STR);                                 \
        float* sVb_ = sV + (buf) * (FN * SV_STR);                                 \
        const size_t kvb_ = ((size_t)(b * SEQ + (kt) * FN)) * KVDIM + (size_t)h * (DNOPE + DV); \
        const size_t ckb_ = ((size_t)(b * SEQ + (kt) * FN)) * DKVA + DKVLAT;      \
        _Pragma("unroll")                                                         \
        for (int t_ = 0; t_ < 6; t_++) {                                          \
            int idx_ = tid + t_ * 256;                                            \
            int row_ = idx_ / 48;                                                 \
            int c4_ = (idx_ % 48) * 4;                                            \
            uint32_t d_ = smem_u32(sKb_ + row_ * SK_STR + c4_);                   \
            const float* s_ = (c4_ < DNOPE)                                       \
                ? kvbuf + kvb_ + (size_t)row_ * KVDIM + c4_                       \
                : ckv + ckb_ + (size_t)row_ * DKVA + (c4_ - DNOPE);               \
            asm volatile("cp.async.cg.shared.global [%0], [%1], 16;"              \
                         :: "r"(d_), "l"(s_));                                    \
        }                                                                         \
        _Pragma("unroll")                                                         \
        for (int t_ = 0; t_ < 4; t_++) {                                          \
            int idx_ = tid + t_ * 256;                                            \
            int row_ = idx_ >> 5;                                                 \
            int c4_ = (idx_ & 31) * 4;                                            \
            uint32_t d_ = smem_u32(sVb_ + row_ * SV_STR + c4_);                   \
            const float* s_ = kvbuf + kvb_ + (size_t)row_ * KVDIM + DNOPE + c4_;  \
            asm volatile("cp.async.cg.shared.global [%0], [%1], 16;"              \
                         :: "r"(d_), "l"(s_));                                    \
        }                                                                         \
        asm volatile("cp.async.commit_group;" ::: "memory");                      \
    }

    for (int job = blockIdx.x; job < NJOBS; job += gridDim.x) {
        const int bq = NQT - 1 - (job / (HEADS * BATCH));   // descending work
        const int hb = job % (HEADS * BATCH);
        const int h = hb & (HEADS - 1);
        const int b = hb >> 4;
        const int q0 = bq * FM;

        __syncthreads();   // previous job's smem reads complete before overwrite

        const int nkt = (q0 + FM) / FN;
        LOAD_KV(0, 0);

        // Q tile (scaled + rounded)
        const size_t qbase = ((size_t)(b * SEQ + q0)) * QDIM + (size_t)h * DQK;
        for (int e = tid; e < FM * (DQK / 4); e += 256) {
            int r = e / (DQK / 4), c4 = (e - r * (DQK / 4)) * 4;
            float4 v = *(const float4*)(q + qbase + (size_t)r * QDIM + c4);
            sQ[r * SQ_STR + c4 + 0] = to_tf32(v.x * ATT_SCALE);
            sQ[r * SQ_STR + c4 + 1] = to_tf32(v.y * ATT_SCALE);
            sQ[r * SQ_STR + c4 + 2] = to_tf32(v.z * ATT_SCALE);
            sQ[r * SQ_STR + c4 + 3] = to_tf32(v.w * ATT_SCALE);
        }

        float o[16][4];
#pragma unroll
        for (int nt = 0; nt < 16; nt++)
#pragma unroll
            for (int i = 0; i < 4; i++) o[nt][i] = 0.f;
        float m0 = -1e30f, m1 = -1e30f, l0 = 0.f, l1 = 0.f;

        for (int kt = 0; kt < nkt; kt++) {
            __syncthreads();
            if (kt + 1 < nkt) {
                LOAD_KV(kt + 1, (kt + 1) & 1);
                asm volatile("cp.async.wait_group 1;" ::: "memory");
            } else {
                asm volatile("cp.async.wait_group 0;" ::: "memory");
            }
            __syncthreads();

            float* sKb = sK + (kt & 1) * (FN * SK_STR);
            float* sVb = sV + (kt & 1) * (FN * SV_STR);
            const uint32_t kBase = smem_u32(sKb + kRowOff);

            float s[4][4];
#pragma unroll
            for (int nt = 0; nt < 4; nt++)
#pragma unroll
                for (int i = 0; i < 4; i++) s[nt][i] = 0.f;

#pragma unroll 4
            for (int ks = 0; ks < DQK / 8; ks++) {
                const uint32_t kOff = ks * 32;
                uint32_t a[4];
                ldsm_x4(a, qBase + kOff);
#pragma unroll
                for (int nt2 = 0; nt2 < 2; nt2++) {
                    uint32_t b4[4];
                    ldsm_x4(b4, kBase + nt2 * (16 * SK_STR * 4) + kOff);
                    mma_tf32(s[nt2 * 2],     a, &b4[0]);
                    mma_tf32(s[nt2 * 2 + 1], a, &b4[2]);
                }
            }

            if (kt * FN + FN - 1 > q0) {
                const int gr0 = q0 + wrow + g;
                const int gr1 = gr0 + 8;
#pragma unroll
                for (int nt = 0; nt < 4; nt++) {
                    int gc = kt * FN + nt * 8 + 2 * tg;
                    if (gc     > gr0) s[nt][0] = -1e30f;
                    if (gc + 1 > gr0) s[nt][1] = -1e30f;
                    if (gc     > gr1) s[nt][2] = -1e30f;
                    if (gc + 1 > gr1) s[nt][3] = -1e30f;
                }
            }

            float mx0 = -1e30f, mx1 = -1e30f;
#pragma unroll
            for (int nt = 0; nt < 4; nt++) {
                mx0 = fmaxf(mx0, fmaxf(s[nt][0], s[nt][1]));
                mx1 = fmaxf(mx1, fmaxf(s[nt][2], s[nt][3]));
            }
#pragma unroll
            for (int o_ = 1; o_ < 4; o_ <<= 1) {
                mx0 = fmaxf(mx0, __shfl_xor_sync(0xffffffffu, mx0, o_));
                mx1 = fmaxf(mx1, __shfl_xor_sync(0xffffffffu, mx1, o_));
            }
            const float mn0 = fmaxf(m0, mx0);
            const float mn1 = fmaxf(m1, mx1);
            const float sc0 = __expf(m0 - mn0);
            const float sc1 = __expf(m1 - mn1);
            float rs0 = 0.f, rs1 = 0.f;
#pragma unroll
            for (int nt = 0; nt < 4; nt++) {
                s[nt][0] = __expf(s[nt][0] - mn0);
                s[nt][1] = __expf(s[nt][1] - mn0);
                s[nt][2] = __expf(s[nt][2] - mn1);
                s[nt][3] = __expf(s[nt][3] - mn1);
                rs0 += s[nt][0] + s[nt][1];
                rs1 += s[nt][2] + s[nt][3];
            }
#pragma unroll
            for (int o_ = 1; o_ < 4; o_ <<= 1) {
                rs0 += __shfl_xor_sync(0xffffffffu, rs0, o_);
                rs1 += __shfl_xor_sync(0xffffffffu, rs1, o_);
            }
            l0 = l0 * sc0 + rs0;  m0 = mn0;
            l1 = l1 * sc1 + rs1;  m1 = mn1;
#pragma unroll
            for (int nt = 0; nt < 16; nt++) {
                o[nt][0] *= sc0; o[nt][1] *= sc0;
                o[nt][2] *= sc1; o[nt][3] *= sc1;
            }
#pragma unroll
            for (int nt = 0; nt < 4; nt++) {
                int col = nt * 8 + 2 * tg;
                sP[(wrow + g    ) * SP_STR + col]     = to_tf32(s[nt][0]);
                sP[(wrow + g    ) * SP_STR + col + 1] = to_tf32(s[nt][1]);
                sP[(wrow + g + 8) * SP_STR + col]     = to_tf32(s[nt][2]);
                sP[(wrow + g + 8) * SP_STR + col + 1] = to_tf32(s[nt][3]);
            }
            __syncwarp();

#pragma unroll
            for (int ks = 0; ks < FN / 8; ks++) {
                const int kb = ks * 8;
                uint32_t a[4];
                ldsm_x4(a, pBase + ks * 32);
#pragma unroll
                for (int nt = 0; nt < 16; nt++) {
                    uint32_t bb[2];
                    bb[0] = __float_as_uint(sVb[(kb + tg    ) * SV_STR + nt * 8 + g]);
                    bb[1] = __float_as_uint(sVb[(kb + tg + 4) * SV_STR + nt * 8 + g]);
                    mma_tf32(o[nt], a, bb);
                }
            }
        }

        // epilogue: tf32-rounded (feeds o-proj GEMM)
        const float inv0 = 1.f / l0, inv1 = 1.f / l1;
        const size_t obase = ((size_t)(b * SEQ + q0)) * ODIM + (size_t)h * DV;
        const size_t r0 = obase + (size_t)(wrow + g) * ODIM;
        const size_t r1 = obase + (size_t)(wrow + g + 8) * ODIM;
#pragma unroll
        for (int nt = 0; nt < 16; nt++) {
            int col = nt * 8 + 2 * tg;
            *(float2*)(attn_out + r0 + col) = make_float2(to_tf32(o[nt][0] * inv0), to_tf32(o[nt][1] * inv0));
            *(float2*)(attn_out + r1 + col) = make_float2(to_tf32(o[nt][2] * inv1), to_tf32(o[nt][3] * inv1));
        }
    }
#undef LOAD_KV
}

// ---------------- launch ----------------
extern "C" void kernel_launch(void* const* d_in, const int* in_sizes, int n_in,
                              void* d_out, int out_size)
{
    (void)in_sizes; (void)n_in; (void)out_size;
    const float* hidden  = (const float*)d_in[0];
    const float* cosb    = (const float*)d_in[1];
    const float* sinb    = (const float*)d_in[2];
    const float* q_a_W   = (const float*)d_in[3];
    const float* q_a_nw  = (const float*)d_in[4];
    const float* q_b_W   = (const float*)d_in[5];
    const float* kv_a_W  = (const float*)d_in[6];
    const float* kv_a_nw = (const float*)d_in[7];
    const float* kv_b_W  = (const float*)d_in[8];
    const float* o_W     = (const float*)d_in[9];
    float* out = (float*)d_out;

    float *qa, *ckv, *kvn, *qbuf, *kvbuf, *attn;
    float *hid_r, *w_qa, *w_kva, *w_qb, *w_kvb, *w_o;
    cudaGetSymbolAddress((void**)&qa,    g_qa);
    cudaGetSymbolAddress((void**)&ckv,   g_ckv);
    cudaGetSymbolAddress((void**)&kvn,   g_kvn);
    cudaGetSymbolAddress((void**)&qbuf,  g_q);
    cudaGetSymbolAddress((void**)&kvbuf, g_kv);
    cudaGetSymbolAddress((void**)&attn,  g_attn);
    cudaGetSymbolAddress((void**)&hid_r, g_hid_r);
    cudaGetSymbolAddress((void**)&w_qa,  g_w_qa);
    cudaGetSymbolAddress((void**)&w_kva, g_w_kva);
    cudaGetSymbolAddress((void**)&w_qb,  g_w_qb);
    cudaGetSymbolAddress((void**)&w_kvb, g_w_kvb);
    cudaGetSymbolAddress((void**)&w_o,   g_w_o);

    cudaFuncSetAttribute(gemm_persist, cudaFuncAttributeMaxDynamicSharedMemorySize, GEMM_SMEM);
    cudaFuncSetAttribute(flash_tf32_kernel, cudaFuncAttributeMaxDynamicSharedMemorySize, FLASH_SMEM);

    // launch 0: fused tf32 rna-rounding of all GEMM inputs
    {
        const int n0 = (int)((size_t)NTOK * DMODEL / 4);
        const int n1 = (int)((size_t)DQA * DMODEL / 4);
        const int n2 = (int)((size_t)DKVA * DMODEL / 4);
        const int n3 = (int)((size_t)QDIM * DQA / 4);
        const int n4 = (int)((size_t)KVDIM * DKVLAT / 4);
        const int n5 = (int)((size_t)DMODEL * ODIM / 4);
        const int total = n0 + n1 + n2 + n3 + n4 + n5;
        round_all_kernel<<<(total + 255) / 256, 256>>>(
            hidden, hid_r, n0,  q_a_W, w_qa, n1,  kv_a_W, w_kva, n2,
            q_b_W,  w_qb, n3,   kv_b_W, w_kvb, n4, o_W,    w_o,  n5);
    }

    // launch 1: PERSISTENT fused q_a ∪ kv_a
    {
        const int gx1 = DQA / TBN;                       // 12
        const int nt1 = gx1 * (NTOK / TBM);              // 384
        const int gx2 = (DKVA + TBN - 1) / TBN;          // 5
        const int nt2 = gx2 * (NTOK / TBM);              // 160
        const int grid = (nt1 + nt2 < GEMM_SLOTS) ? (nt1 + nt2) : GEMM_SLOTS;
        gemm_persist<<<grid, 256, GEMM_SMEM>>>(
            hid_r, w_qa, qa, DQA, DMODEL, nt1, gx1, 0,
            hid_r, w_kva, ckv, DKVA, DMODEL, nt2, gx2, 0);
    }

    // launch 2: FUSED dual rmsnorm
    rmsnorm_dual_kernel<<<2 * NTOK, 256>>>(
        qa, qa, q_a_nw, DQA, DQA, DQA, NTOK,
        ckv, kvn, kv_a_nw, DKVLAT, DKVA, DKVLAT);

    // launch 3: PERSISTENT fused q_b (raw out) ∪ kv_b (tf32-rounded out)
    {
        const int gx1 = QDIM / TBN;                      // 24
        const int nt1 = gx1 * (NTOK / TBM);              // 768
        const int gx2 = KVDIM / TBN;                     // 32
        const int nt2 = gx2 * (NTOK / TBM);              // 1024
        gemm_persist<<<GEMM_SLOTS, 256, GEMM_SMEM>>>(
            qa, w_qb, qbuf, QDIM, DQA, nt1, gx1, 0,
            kvn, w_kvb, kvbuf, KVDIM, DKVLAT, nt2, gx2, 1);
    }

    // launch 4: RoPE (ckv slice rounded)
    rope_kernel<<<NTOK, 512>>>(qbuf, ckv, cosb, sinb);

    // launch 5: PERSISTENT flash attention (148 CTAs, jobs bq-descending)
    flash_tf32_kernel<<<NSM, 256, FLASH_SMEM>>>(qbuf, kvbuf, ckv, attn);

    // launch 6: PERSISTENT o-proj
    {
        const int gx = DMODEL / TBN;                     // 16
        const int nt = gx * (NTOK / TBM);                // 512
        const int grid = (nt < GEMM_SLOTS) ? nt : GEMM_SLOTS;
        gemm_persist<<<grid, 256, GEMM_SMEM>>>(
            attn, w_o, out, DMODEL, ODIM, nt, gx, 0,
            attn, w_o, out, DMODEL, ODIM, 0, gx, 0);
    }
}

// round 16
// speedup vs baseline: 1.1009x; 1.1009x over previous
#include <cuda_runtime.h>
#include <cuda_bf16.h>
#include <math.h>
#include <stdint.h>

// ---------------- problem constants ----------------
#define BATCH   2
#define SEQ     2048
#define NTOK    (BATCH * SEQ)        // 4096
#define DMODEL  2048
#define HEADS   16
#define DQK     192
#define DNOPE   128
#define DROPE   64
#define DV      128
#define DQA     1536
#define DKVA    576
#define DKVLAT  512
#define QDIM    (HEADS * DQK)        // 3072
#define KVDIM   (HEADS * (DNOPE + DV)) // 4096
#define ODIM    (HEADS * DV)         // 2048
#define ATT_SCALE 0.07216878364870322f

// ---------------- scratch ----------------
__device__ float g_qa  [(size_t)NTOK * DQA];
__device__ float g_ckv [(size_t)NTOK * DKVA];
__device__ float g_kvn [(size_t)NTOK * DKVLAT];
__device__ float g_q   [(size_t)NTOK * QDIM];
__device__ float g_kv  [(size_t)NTOK * KVDIM];
__device__ float g_attn[(size_t)NTOK * ODIM];
// tf32-rounded copies (GEMM inner loop consumes raw bits; round upstream)
__device__ float g_hid_r [(size_t)NTOK * DMODEL];
__device__ float g_w_qa  [(size_t)DQA * DMODEL];
__device__ float g_w_kva [(size_t)DKVA * DMODEL];
__device__ float g_w_qb  [(size_t)QDIM * DQA];
__device__ float g_w_kvb [(size_t)KVDIM * DKVLAT];
__device__ float g_w_o   [(size_t)DMODEL * ODIM];

// ---------------- helpers ----------------
__device__ __forceinline__ float to_tf32(float x) {
    float y;
    asm("cvt.rna.tf32.f32 %0, %1;" : "=f"(y) : "f"(x));
    return y;
}

__device__ __forceinline__ uint32_t smem_u32(const void* p) {
    uint32_t a;
    asm("{ .reg .u64 t; cvta.to.shared.u64 t, %1; cvt.u32.u64 %0, t; }" : "=r"(a) : "l"(p));
    return a;
}

__device__ __forceinline__ void mma_tf32(float c[4], const uint32_t a[4], const uint32_t b[2]) {
    asm volatile(
        "mma.sync.aligned.m16n8k8.row.col.f32.tf32.tf32.f32 "
        "{%0,%1,%2,%3}, {%4,%5,%6,%7}, {%8,%9}, {%0,%1,%2,%3};\n"
        : "+f"(c[0]), "+f"(c[1]), "+f"(c[2]), "+f"(c[3])
        : "r"(a[0]), "r"(a[1]), "r"(a[2]), "r"(a[3]), "r"(b[0]), "r"(b[1]));
}

__device__ __forceinline__ void ldsm_x4(uint32_t r[4], uint32_t addr) {
    asm volatile("ldmatrix.sync.aligned.m8n8.x4.shared.b16 {%0,%1,%2,%3}, [%4];"
        : "=r"(r[0]), "=r"(r[1]), "=r"(r[2]), "=r"(r[3]) : "r"(addr));
}

// ---------------- unified dynamic smem ----------------
extern __shared__ char dynsm[];

// ============================================================================
// TF32 GEMM tile body (mma.sync + ldmatrix, 3-stage cp.async pipeline)
// Computes C[bm:bm+128, bn:bn+128] = A[bm:,:K] @ B[bn:,:K]^T
// Inputs MUST be pre-rounded to tf32 (rna). If do_round, output is rna-rounded.
// ============================================================================
#define TBM 128
#define TBN 128
#define TBK 32
#define ASTR 36                          // row stride 144B -> ldmatrix conflict-free
#define NSTG 3
#define STG_FLOATS (TBM * ASTR + TBN * ASTR)   // 9216 floats per stage
#define GEMM_SMEM (NSTG * STG_FLOATS * (int)sizeof(float))  // 110592 B

__device__ __forceinline__ void gemm_tile_body(
    const float* __restrict__ A, const float* __restrict__ Bw,
    float* __restrict__ C, int N, int K, int bm, int bn, int do_round)
{
    float* sm = (float*)dynsm;
    const int tid = threadIdx.x;
    const int wid = tid >> 5, lane = tid & 31;
    const int g = lane >> 2, tg = lane & 3;
    const int wm = (wid >> 2) * 64, wn = (wid & 3) * 32;
    const int NK = K / TBK;

    const int aRowOff = (wm + ((lane >> 3) & 1) * 8 + (lane & 7)) * ASTR + (lane >> 4) * 4;
    const int bRowOff = (wn + (lane >> 4) * 8 + (lane & 7)) * ASTR + ((lane >> 3) & 1) * 4;

#define LOAD_STAGE(c)                                                             \
    {                                                                             \
        const int s_ = (c) % NSTG;                                                \
        float* as_ = sm + s_ * STG_FLOATS;                                        \
        float* bs_ = as_ + TBM * ASTR;                                            \
        _Pragma("unroll")                                                         \
        for (int t_ = 0; t_ < 4; t_++) {                                          \
            int idx_ = tid + t_ * 256;                                            \
            int row_ = idx_ >> 3;                                                 \
            int c4_ = (idx_ & 7) * 4;                                             \
            uint32_t d_ = smem_u32(as_ + row_ * ASTR + c4_);                      \
            const float* s1_ = A + (size_t)(bm + row_) * K + (size_t)(c) * TBK + c4_; \
            asm volatile("cp.async.cg.shared.global.L2::256B [%0], [%1], 16;"     \
                         :: "r"(d_), "l"(s1_));                                   \
        }                                                                         \
        _Pragma("unroll")                                                         \
        for (int t_ = 0; t_ < 4; t_++) {                                          \
            int idx_ = tid + t_ * 256;                                            \
            int row_ = idx_ >> 3;                                                 \
            int c4_ = (idx_ & 7) * 4;                                             \
            int nr_ = bn + row_;                                                  \
            uint32_t d_ = smem_u32(bs_ + row_ * ASTR + c4_);                      \
            const float* s1_ = Bw + (size_t)(nr_ < N ? nr_ : 0) * K + (size_t)(c) * TBK + c4_; \
            unsigned sz_ = (nr_ < N) ? 16u : 0u;                                  \
            asm volatile("cp.async.cg.shared.global.L2::256B [%0], [%1], 16, %2;" \
                         :: "r"(d_), "l"(s1_), "r"(sz_));                         \
        }                                                                         \
        asm volatile("cp.async.commit_group;" ::: "memory");                      \
    }

    float acc[4][4][4];
#pragma unroll
    for (int mt = 0; mt < 4; mt++)
#pragma unroll
        for (int nt = 0; nt < 4; nt++)
#pragma unroll
            for (int i = 0; i < 4; i++) acc[mt][nt][i] = 0.f;

    LOAD_STAGE(0);
    LOAD_STAGE(1);

    for (int cc = 0; cc < NK; cc++) {
        // remainder-aware wait: the chunk being consumed must be fully landed
        if (cc + 1 < NK) asm volatile("cp.async.wait_group 1;" ::: "memory");
        else             asm volatile("cp.async.wait_group 0;" ::: "memory");
        __syncthreads();
        if (cc + 2 < NK) LOAD_STAGE(cc + 2);

        const int s = cc % NSTG;
        float* as_ = sm + s * STG_FLOATS;
        float* bs_ = as_ + TBM * ASTR;
        const uint32_t aBase = smem_u32(as_ + aRowOff);
        const uint32_t bBase = smem_u32(bs_ + bRowOff);

#pragma unroll
        for (int ks = 0; ks < 4; ks++) {
            const uint32_t kOff = ks * 32;
            uint32_t a[4][4], b[8];
#pragma unroll
            for (int mt = 0; mt < 4; mt++)
                ldsm_x4(a[mt], aBase + mt * (16 * ASTR * 4) + kOff);
            ldsm_x4(&b[0], bBase + kOff);
            ldsm_x4(&b[4], bBase + 16 * ASTR * 4 + kOff);
#pragma unroll
            for (int mt = 0; mt < 4; mt++)
#pragma unroll
                for (int nt = 0; nt < 4; nt++)
                    mma_tf32(acc[mt][nt], a[mt], &b[nt * 2]);
        }
    }

#pragma unroll
    for (int mt = 0; mt < 4; mt++) {
        int r0 = bm + wm + mt * 16 + g;
#pragma unroll
        for (int nt = 0; nt < 4; nt++) {
            int cc = bn + wn + nt * 8 + 2 * tg;
            if (cc < N) {
                float2 v0 = make_float2(acc[mt][nt][0], acc[mt][nt][1]);
                float2 v1 = make_float2(acc[mt][nt][2], acc[mt][nt][3]);
                if (do_round) {
                    v0.x = to_tf32(v0.x); v0.y = to_tf32(v0.y);
                    v1.x = to_tf32(v1.x); v1.y = to_tf32(v1.y);
                }
                *(float2*)(C + (size_t)r0 * N + cc)       = v0;
                *(float2*)(C + (size_t)(r0 + 8) * N + cc) = v1;
            }
        }
    }
#undef LOAD_STAGE
}

// single GEMM launch
__global__ __launch_bounds__(256, 2) void gemm_tf32(
    const float* __restrict__ A, const float* __restrict__ Bw,
    float* __restrict__ C, int M, int N, int K, int do_round)
{
    (void)M;
    gemm_tile_body(A, Bw, C, N, K, blockIdx.y * TBM, blockIdx.x * TBN, do_round);
}

// fused dual GEMM (flattened 1-D grid; blockIdx selects GEMM + tile)
__global__ __launch_bounds__(256, 2) void gemm_dual(
    const float* __restrict__ A1, const float* __restrict__ B1, float* __restrict__ C1,
    int N1, int K1, int ntiles1, int gx1, int round1,
    const float* __restrict__ A2, const float* __restrict__ B2, float* __restrict__ C2,
    int N2, int K2, int gx2, int round2)
{
    int t = blockIdx.x;
    const float *A, *Bw;
    float* C;
    int N, K, bm, bn, rnd;
    if (t < ntiles1) {
        A = A1; Bw = B1; C = C1; N = N1; K = K1; rnd = round1;
        bn = (t % gx1) * TBN; bm = (t / gx1) * TBM;
    } else {
        t -= ntiles1;
        A = A2; Bw = B2; C = C2; N = N2; K = K2; rnd = round2;
        bn = (t % gx2) * TBN; bm = (t / gx2) * TBM;
    }
    gemm_tile_body(A, Bw, C, N, K, bm, bn, rnd);
}

// ---------------- fused tf32 pre-rounding pass (ALL buffers, one launch) ---
__device__ __forceinline__ void round4(const float* in, float* out, int i) {
    float4 v = ((const float4*)in)[i];
    v.x = to_tf32(v.x); v.y = to_tf32(v.y);
    v.z = to_tf32(v.z); v.w = to_tf32(v.w);
    ((float4*)out)[i] = v;
}

__global__ __launch_bounds__(256) void round_all_kernel(
    const float* s0, float* d0, int n0,
    const float* s1, float* d1, int n1,
    const float* s2, float* d2, int n2,
    const float* s3, float* d3, int n3,
    const float* s4, float* d4, int n4,
    const float* s5, float* d5, int n5)
{
    int i = blockIdx.x * 256 + threadIdx.x;
    if (i < n0) { round4(s0, d0, i); return; }  i -= n0;
    if (i < n1) { round4(s1, d1, i); return; }  i -= n1;
    if (i < n2) { round4(s2, d2, i); return; }  i -= n2;
    if (i < n3) { round4(s3, d3, i); return; }  i -= n3;
    if (i < n4) { round4(s4, d4, i); return; }  i -= n4;
    if (i < n5) { round4(s5, d5, i); }
}

// ---------------- fused dual RMSNorm (tf32-rounded output) -----------------
__global__ __launch_bounds__(256) void rmsnorm_dual_kernel(
    const float* __restrict__ in1, float* __restrict__ out1,
    const float* __restrict__ w1, int N1, int is1, int os1, int rows1,
    const float* __restrict__ in2, float* __restrict__ out2,
    const float* __restrict__ w2, int N2, int is2, int os2)
{
    const float* in;  float* out;  const float* w;
    int N, in_stride, out_stride, row = blockIdx.x;
    if (row < rows1) { in = in1; out = out1; w = w1; N = N1; in_stride = is1; out_stride = os1; }
    else { row -= rows1; in = in2; out = out2; w = w2; N = N2; in_stride = is2; out_stride = os2; }

    const float* x = in + (size_t)row * in_stride;
    const int cnt = N >> 8;
    float v[6];
    float ss = 0.f;
    for (int i = 0; i < cnt; i++) {
        v[i] = x[threadIdx.x + (i << 8)];
        ss += v[i] * v[i];
    }
#pragma unroll
    for (int o = 16; o > 0; o >>= 1) ss += __shfl_xor_sync(0xffffffffu, ss, o);
    __shared__ float red[8];
    if ((threadIdx.x & 31) == 0) red[threadIdx.x >> 5] = ss;
    __syncthreads();
    float tot = 0.f;
#pragma unroll
    for (int i = 0; i < 8; i++) tot += red[i];
    const float r = rsqrtf(tot / (float)N + 1e-6f);
    float* y = out + (size_t)row * out_stride;
    for (int i = 0; i < cnt; i++) {
        int c = threadIdx.x + (i << 8);
        y[c] = to_tf32(w[c] * v[i] * r);
    }
}

// ---------------- RoPE (ckv slice written tf32-rounded; q slice raw) -------
__global__ __launch_bounds__(512) void rope_kernel(
    float* __restrict__ q, float* __restrict__ ckv,
    const float* __restrict__ cosb, const float* __restrict__ sinb)
{
    const int tok = blockIdx.x;
    const int t = threadIdx.x;
    const int h = t >> 5;
    const int d = t & 31;
    const float c0 = cosb[(size_t)tok * DROPE + d];
    const float s0 = sinb[(size_t)tok * DROPE + d];
    const float c1 = cosb[(size_t)tok * DROPE + d + 32];
    const float s1 = sinb[(size_t)tok * DROPE + d + 32];
    {
        float* qr = q + (size_t)tok * QDIM + h * DQK + DNOPE;
        float a = qr[d], b = qr[d + 32];
        qr[d]      = a * c0 - b * s0;
        qr[d + 32] = b * c1 + a * s1;
    }
    if (t < 32) {
        float* kr = ckv + (size_t)tok * DKVA + DKVLAT;
        float a = kr[d], b = kr[d + 32];
        kr[d]      = to_tf32(a * c0 - b * s0);   // consumed raw by flash K (cp.async)
        kr[d + 32] = to_tf32(b * c1 + a * s1);
    }
}

// ---------------- Flash attention (R14 config: non-persistent) -------------
// FM=128, FN=32, cp.async double-buffered K/V (pre-rounded in gmem),
// Q loaded synchronously (scaled+rounded).
#define FM 128
#define FN 32
#define SQ_STR 196   // %32 == 4
#define SK_STR 196   // %32 == 4
#define SV_STR 136   // natural V [k][dv], %32 == 8
#define SP_STR 36    // %32 == 4
#define FLASH_SMEM ((FM * SQ_STR + 2 * FN * SK_STR + 2 * FN * SV_STR + FM * SP_STR) * (int)sizeof(float))

__global__ __launch_bounds__(256) void flash_tf32_kernel(
    const float* __restrict__ q, const float* __restrict__ kvbuf,
    const float* __restrict__ ckv, float* __restrict__ attn_out)
{
    float* fsmem = (float*)dynsm;
    float* sQ = fsmem;                        // 128 x 196
    float* sK = sQ + FM * SQ_STR;             // 2 x 32 x 196
    float* sV = sK + 2 * FN * SK_STR;         // 2 x 32 x 136
    float* sP = sV + 2 * FN * SV_STR;         // 128 x 36

    const int bq = gridDim.x - 1 - blockIdx.x;   // longest tiles first
    const int h  = blockIdx.y;
    const int b  = blockIdx.z;
    const int q0 = bq * FM;
    const int tid = threadIdx.x;
    const int wid = tid >> 5, lane = tid & 31;
    const int g = lane >> 2, tg = lane & 3;
    const int wrow = wid * 16;

    const int aSel = ((lane >> 3) & 1) * 8 + (lane & 7);
    const int aCol = (lane >> 4) * 4;
    const int bSel = (lane >> 4) * 8 + (lane & 7);
    const int bCol = ((lane >> 3) & 1) * 4;

    const uint32_t qBase = smem_u32(sQ + (wrow + aSel) * SQ_STR + aCol);
    const uint32_t pBase = smem_u32(sP + (wrow + aSel) * SP_STR + aCol);
    const int kRowOff = bSel * SK_STR + bCol;

#define LOAD_KV(kt, buf)                                                          \
    {                                                                             \
        float* sKb_ = sK + (buf) * (FN * SK_STR);                                 \
        float* sVb_ = sV + (buf) * (FN * SV_STR);                                 \
        const size_t kvb_ = ((size_t)(b * SEQ + (kt) * FN)) * KVDIM + (size_t)h * (DNOPE + DV); \
        const size_t ckb_ = ((size_t)(b * SEQ + (kt) * FN)) * DKVA + DKVLAT;      \
        _Pragma("unroll")                                                         \
        for (int t_ = 0; t_ < 6; t_++) {                                          \
            int idx_ = tid + t_ * 256;                                            \
            int row_ = idx_ / 48;                                                 \
            int c4_ = (idx_ % 48) * 4;                                            \
            uint32_t d_ = smem_u32(sKb_ + row_ * SK_STR + c4_);                   \
            const float* s_ = (c4_ < DNOPE)                                       \
                ? kvbuf + kvb_ + (size_t)row_ * KVDIM + c4_                       \
                : ckv + ckb_ + (size_t)row_ * DKVA + (c4_ - DNOPE);               \
            asm volatile("cp.async.cg.shared.global [%0], [%1], 16;"              \
                         :: "r"(d_), "l"(s_));                                    \
        }                                                                         \
        _Pragma("unroll")                                                         \
        for (int t_ = 0; t_ < 4; t_++) {                                          \
            int idx_ = tid + t_ * 256;                                            \
            int row_ = idx_ >> 5;                                                 \
            int c4_ = (idx_ & 31) * 4;                                            \
            uint32_t d_ = smem_u32(sVb_ + row_ * SV_STR + c4_);                   \
            const float* s_ = kvbuf + kvb_ + (size_t)row_ * KVDIM + DNOPE + c4_;  \
            asm volatile("cp.async.cg.shared.global [%0], [%1], 16;"              \
                         :: "r"(d_), "l"(s_));                                    \
        }                                                                         \
        asm volatile("cp.async.commit_group;" ::: "memory");                      \
    }

    // Q tile (scaled + rounded)
    const size_t qbase = ((size_t)(b * SEQ + q0)) * QDIM + (size_t)h * DQK;
    for (int e = tid; e < FM * (DQK / 4); e += 256) {
        int r = e / (DQK / 4), c4 = (e - r * (DQK / 4)) * 4;
        float4 v = *(const float4*)(q + qbase + (size_t)r * QDIM + c4);
        sQ[r * SQ_STR + c4 + 0] = to_tf32(v.x * ATT_SCALE);
        sQ[r * SQ_STR + c4 + 1] = to_tf32(v.y * ATT_SCALE);
        sQ[r * SQ_STR + c4 + 2] = to_tf32(v.z * ATT_SCALE);
        sQ[r * SQ_STR + c4 + 3] = to_tf32(v.w * ATT_SCALE);
    }

    float o[16][4];
#pragma unroll
    for (int nt = 0; nt < 16; nt++)
#pragma unroll
        for (int i = 0; i < 4; i++) o[nt][i] = 0.f;
    float m0 = -1e30f, m1 = -1e30f, l0 = 0.f, l1 = 0.f;

    const int nkt = (q0 + FM) / FN;
    LOAD_KV(0, 0);

    for (int kt = 0; kt < nkt; kt++) {
        __syncthreads();   // all warps done with the buffer being overwritten
        if (kt + 1 < nkt) {
            LOAD_KV(kt + 1, (kt + 1) & 1);
            asm volatile("cp.async.wait_group 1;" ::: "memory");
        } else {
            asm volatile("cp.async.wait_group 0;" ::: "memory");
        }
        __syncthreads();   // tile kt visible to all warps (and Q on kt==0)

        float* sKb = sK + (kt & 1) * (FN * SK_STR);
        float* sVb = sV + (kt & 1) * (FN * SV_STR);
        const uint32_t kBase = smem_u32(sKb + kRowOff);

        // ---- S = Q K^T : warp 16 x 32 (4 n-tiles) ----
        float s[4][4];
#pragma unroll
        for (int nt = 0; nt < 4; nt++)
#pragma unroll
            for (int i = 0; i < 4; i++) s[nt][i] = 0.f;

#pragma unroll 4
        for (int ks = 0; ks < DQK / 8; ks++) {
            const uint32_t kOff = ks * 32;
            uint32_t a[4];
            ldsm_x4(a, qBase + kOff);
#pragma unroll
            for (int nt2 = 0; nt2 < 2; nt2++) {
                uint32_t b4[4];
                ldsm_x4(b4, kBase + nt2 * (16 * SK_STR * 4) + kOff);
                mma_tf32(s[nt2 * 2],     a, &b4[0]);
                mma_tf32(s[nt2 * 2 + 1], a, &b4[2]);
            }
        }

        if (kt * FN + FN - 1 > q0) {
            const int gr0 = q0 + wrow + g;
            const int gr1 = gr0 + 8;
#pragma unroll
            for (int nt = 0; nt < 4; nt++) {
                int gc = kt * FN + nt * 8 + 2 * tg;
                if (gc     > gr0) s[nt][0] = -1e30f;
                if (gc + 1 > gr0) s[nt][1] = -1e30f;
                if (gc     > gr1) s[nt][2] = -1e30f;
                if (gc + 1 > gr1) s[nt][3] = -1e30f;
            }
        }

        // ---- online softmax ----
        float mx0 = -1e30f, mx1 = -1e30f;
#pragma unroll
        for (int nt = 0; nt < 4; nt++) {
            mx0 = fmaxf(mx0, fmaxf(s[nt][0], s[nt][1]));
            mx1 = fmaxf(mx1, fmaxf(s[nt][2], s[nt][3]));
        }
#pragma unroll
        for (int o_ = 1; o_ < 4; o_ <<= 1) {
            mx0 = fmaxf(mx0, __shfl_xor_sync(0xffffffffu, mx0, o_));
            mx1 = fmaxf(mx1, __shfl_xor_sync(0xffffffffu, mx1, o_));
        }
        const float mn0 = fmaxf(m0, mx0);
        const float mn1 = fmaxf(m1, mx1);
        const float sc0 = __expf(m0 - mn0);
        const float sc1 = __expf(m1 - mn1);
        float rs0 = 0.f, rs1 = 0.f;
#pragma unroll
        for (int nt = 0; nt < 4; nt++) {
            s[nt][0] = __expf(s[nt][0] - mn0);
            s[nt][1] = __expf(s[nt][1] - mn0);
            s[nt][2] = __expf(s[nt][2] - mn1);
            s[nt][3] = __expf(s[nt][3] - mn1);
            rs0 += s[nt][0] + s[nt][1];
            rs1 += s[nt][2] + s[nt][3];
        }
#pragma unroll
        for (int o_ = 1; o_ < 4; o_ <<= 1) {
            rs0 += __shfl_xor_sync(0xffffffffu, rs0, o_);
            rs1 += __shfl_xor_sync(0xffffffffu, rs1, o_);
        }
        l0 = l0 * sc0 + rs0;  m0 = mn0;
        l1 = l1 * sc1 + rs1;  m1 = mn1;
#pragma unroll
        for (int nt = 0; nt < 16; nt++) {
            o[nt][0] *= sc0; o[nt][1] *= sc0;
            o[nt][2] *= sc1; o[nt][3] *= sc1;
        }
#pragma unroll
        for (int nt = 0; nt < 4; nt++) {
            int col = nt * 8 + 2 * tg;
            sP[(wrow + g    ) * SP_STR + col]     = to_tf32(s[nt][0]);
            sP[(wrow + g    ) * SP_STR + col + 1] = to_tf32(s[nt][1]);
            sP[(wrow + g + 8) * SP_STR + col]     = to_tf32(s[nt][2]);
            sP[(wrow + g + 8) * SP_STR + col + 1] = to_tf32(s[nt][3]);
        }
        __syncwarp();

        // ---- O += P V : 16 n-tiles over DV, K=32 (P via ldmatrix, V scalar) ----
#pragma unroll
        for (int ks = 0; ks < FN / 8; ks++) {
            const int kb = ks * 8;
            uint32_t a[4];
            ldsm_x4(a, pBase + ks * 32);
#pragma unroll
            for (int nt = 0; nt < 16; nt++) {
                uint32_t bb[2];
                bb[0] = __float_as_uint(sVb[(kb + tg    ) * SV_STR + nt * 8 + g]);
                bb[1] = __float_as_uint(sVb[(kb + tg + 4) * SV_STR + nt * 8 + g]);
                mma_tf32(o[nt], a, bb);
            }
        }
    }

    // epilogue: tf32-rounded (feeds o-proj GEMM which consumes raw bits)
    const float inv0 = 1.f / l0, inv1 = 1.f / l1;
    const size_t obase = ((size_t)(b * SEQ + q0)) * ODIM + (size_t)h * DV;
    const size_t r0 = obase + (size_t)(wrow + g) * ODIM;
    const size_t r1 = obase + (size_t)(wrow + g + 8) * ODIM;
#pragma unroll
    for (int nt = 0; nt < 16; nt++) {
        int col = nt * 8 + 2 * tg;
        *(float2*)(attn_out + r0 + col) = make_float2(to_tf32(o[nt][0] * inv0), to_tf32(o[nt][1] * inv0));
        *(float2*)(attn_out + r1 + col) = make_float2(to_tf32(o[nt][2] * inv1), to_tf32(o[nt][3] * inv1));
    }
#undef LOAD_KV
}

// ---------------- launch ----------------
extern "C" void kernel_launch(void* const* d_in, const int* in_sizes, int n_in,
                              void* d_out, int out_size)
{
    (void)in_sizes; (void)n_in; (void)out_size;
    const float* hidden  = (const float*)d_in[0];
    const float* cosb    = (const float*)d_in[1];
    const float* sinb    = (const float*)d_in[2];
    const float* q_a_W   = (const float*)d_in[3];
    const float* q_a_nw  = (const float*)d_in[4];
    const float* q_b_W   = (const float*)d_in[5];
    const float* kv_a_W  = (const float*)d_in[6];
    const float* kv_a_nw = (const float*)d_in[7];
    const float* kv_b_W  = (const float*)d_in[8];
    const float* o_W     = (const float*)d_in[9];
    float* out = (float*)d_out;

    float *qa, *ckv, *kvn, *qbuf, *kvbuf, *attn;
    float *hid_r, *w_qa, *w_kva, *w_qb, *w_kvb, *w_o;
    cudaGetSymbolAddress((void**)&qa,    g_qa);
    cudaGetSymbolAddress((void**)&ckv,   g_ckv);
    cudaGetSymbolAddress((void**)&kvn,   g_kvn);
    cudaGetSymbolAddress((void**)&qbuf,  g_q);
    cudaGetSymbolAddress((void**)&kvbuf, g_kv);
    cudaGetSymbolAddress((void**)&attn,  g_attn);
    cudaGetSymbolAddress((void**)&hid_r, g_hid_r);
    cudaGetSymbolAddress((void**)&w_qa,  g_w_qa);
    cudaGetSymbolAddress((void**)&w_kva, g_w_kva);
    cudaGetSymbolAddress((void**)&w_qb,  g_w_qb);
    cudaGetSymbolAddress((void**)&w_kvb, g_w_kvb);
    cudaGetSymbolAddress((void**)&w_o,   g_w_o);

    cudaFuncSetAttribute(gemm_tf32, cudaFuncAttributeMaxDynamicSharedMemorySize, GEMM_SMEM);
    cudaFuncSetAttribute(gemm_dual, cudaFuncAttributeMaxDynamicSharedMemorySize, GEMM_SMEM);
    cudaFuncSetAttribute(flash_tf32_kernel, cudaFuncAttributeMaxDynamicSharedMemorySize, FLASH_SMEM);

    // launch 0: fused tf32 rna-rounding of all GEMM inputs
    {
        const int n0 = (int)((size_t)NTOK * DMODEL / 4);
        const int n1 = (int)((size_t)DQA * DMODEL / 4);
        const int n2 = (int)((size_t)DKVA * DMODEL / 4);
        const int n3 = (int)((size_t)QDIM * DQA / 4);
        const int n4 = (int)((size_t)KVDIM * DKVLAT / 4);
        const int n5 = (int)((size_t)DMODEL * ODIM / 4);
        const int total = n0 + n1 + n2 + n3 + n4 + n5;
        round_all_kernel<<<(total + 255) / 256, 256>>>(
            hidden, hid_r, n0,  q_a_W, w_qa, n1,  kv_a_W, w_kva, n2,
            q_b_W,  w_qb, n3,   kv_b_W, w_kvb, n4, o_W,    w_o,  n5);
    }

    // launch 1: FUSED q_a ∪ kv_a (outputs raw fp32 -> rmsnorm)
    {
        const int gx1 = DQA / TBN;
        const int nt1 = gx1 * (NTOK / TBM);
        const int gx2 = (DKVA + TBN - 1) / TBN;
        const int nt2 = gx2 * (NTOK / TBM);
        gemm_dual<<<nt1 + nt2, 256, GEMM_SMEM>>>(
            hid_r, w_qa, qa, DQA, DMODEL, nt1, gx1, 0,
            hid_r, w_kva, ckv, DKVA, DMODEL, gx2, 0);
    }

    // launch 2: FUSED dual rmsnorm
    rmsnorm_dual_kernel<<<2 * NTOK, 256>>>(
        qa, qa, q_a_nw, DQA, DQA, DQA, NTOK,
        ckv, kvn, kv_a_nw, DKVLAT, DKVA, DKVLAT);

    // launch 3: FUSED q_b (raw out) ∪ kv_b (tf32-rounded out -> flash cp.async)
    {
        const int gx1 = QDIM / TBN;
        const int nt1 = gx1 * (NTOK / TBM);
        const int gx2 = KVDIM / TBN;
        const int nt2 = gx2 * (NTOK / TBM);
        gemm_dual<<<nt1 + nt2, 256, GEMM_SMEM>>>(
            qa, w_qb, qbuf, QDIM, DQA, nt1, gx1, 0,
            kvn, w_kvb, kvbuf, KVDIM, DKVLAT, gx2, 1);
    }

    // launch 4: RoPE (ckv slice rounded)
    rope_kernel<<<NTOK, 512>>>(qbuf, ckv, cosb, sinb);
    // launch 5 (profiler window): flash attention
    flash_tf32_kernel<<<dim3(SEQ / FM, HEADS, BATCH), 256, FLASH_SMEM>>>(qbuf, kvbuf, ckv, attn);
    // launch 6: out = attn @ o_W^T
    gemm_tf32<<<dim3(DMODEL / TBN, NTOK / TBM), 256, GEMM_SMEM>>>(attn, w_o, out, NTOK, DMODEL, ODIM, 0);
}